// round 13
// baseline (speedup 1.0000x reference)
#include <cuda_runtime.h>
#include <cuda_fp16.h>
#include <cstdint>

// ---------------- problem constants ----------------
#define DH        2048
#define KTOT      4096            // concat(x,h) K
#define KC        64              // fp16 per stage K-chunk = 128 bytes (SW128 atom row)
#define KITERS    64              // 4096/64
#define NSTAGE    3
#define MT        64              // CTA M tile
#define NT        64              // CTA N tile
#define A_STG     8192            // A tile bytes per stage (64 rows x 128B, pre-swizzled)
#define B_STG     24576           // B tile bytes per stage (3 gates x 64 rows x 128B)
#define STAGE_BYTES  (A_STG + B_STG)                   // 32768
#define SMEM_TOTAL   (1024 + NSTAGE * STAGE_BYTES)     // 99328  -> 2 CTAs/SM
#define NTHREADS  128

#define A_ELEMS   (8192u * 4096u)          // 33,554,432
#define W_ELEMS   (3u * 2048u * 4096u)     // 25,165,824
#define A_CHUNKS  4194304u                 // 16B chunks in packed A
#define W_CHUNKS  3145728u                 // 16B chunks in packed W
#define TOT_CHUNKS (A_CHUNKS + W_CHUNKS)   // 7,340,032 = 28672 * 256

// ---------------- scratch: packed, tile-major, PRE-SWIZZLED operand store --------------
// A_packed blocks: [m_tile 0..127][kc 0..63] -> 8192 B each (64 rows x 128B)
// W_packed blocks: [n_tile 0..31][kc 0..63] -> 24576 B each, after A (A_ELEMS elems)
__device__ __align__(1024) __half g_AW[A_ELEMS + W_ELEMS];

// ---------------- helpers ----------------
static __device__ __forceinline__ uint32_t smem_u32(const void* p) {
    uint32_t a;
    asm("{ .reg .u64 t; cvta.to.shared.u64 t, %1; cvt.u32.u64 %0, t; }" : "=r"(a) : "l"(p));
    return a;
}
static __device__ __forceinline__ void ldsm4(uint32_t* r, uint32_t addr) {
    asm volatile("ldmatrix.sync.aligned.m8n8.x4.shared.b16 {%0,%1,%2,%3}, [%4];"
                 : "=r"(r[0]), "=r"(r[1]), "=r"(r[2]), "=r"(r[3]) : "r"(addr));
}
static __device__ __forceinline__ void mma16816(float* c4, const uint32_t* a,
                                                uint32_t b0, uint32_t b1) {
    asm volatile(
        "mma.sync.aligned.m16n8k16.row.col.f32.f16.f16.f32 "
        "{%0,%1,%2,%3}, {%4,%5,%6,%7}, {%8,%9}, {%0,%1,%2,%3};"
        : "+f"(c4[0]), "+f"(c4[1]), "+f"(c4[2]), "+f"(c4[3])
        : "r"(a[0]), "r"(a[1]), "r"(a[2]), "r"(a[3]), "r"(b0), "r"(b1));
}
static __device__ __forceinline__ float sigf(float x) {
    return __fdividef(1.f, 1.f + __expf(-x));
}
static __device__ __forceinline__ float tanhe(float x) {
    float t = __expf(2.f * x);
    return __fdividef(t - 1.f, t + 1.f);
}
static __device__ __forceinline__ uint32_t sw128(uint32_t off) {
    return off ^ ((off >> 3) & 0x70);
}

#define MBARRIER_INIT(addr, cnt) \
    asm volatile("mbarrier.init.shared.b64 [%0], %1;" \
        :: "r"((uint32_t)(addr)), "r"((uint32_t)(cnt)) : "memory")
#define MBARRIER_EXPECT_TX(addr, bytes) \
    asm volatile("mbarrier.arrive.expect_tx.shared.b64 _, [%0], %1;" \
        :: "r"((uint32_t)(addr)), "r"((uint32_t)(bytes)) : "memory")
static __device__ __forceinline__ void bulk_cp(uint32_t dst, const void* src,
                                               uint32_t bytes, uint32_t mbar) {
    asm volatile(
        "cp.async.bulk.shared::cluster.global.mbarrier::complete_tx::bytes "
        "[%0], [%1], %2, [%3];"
        :: "r"(dst), "l"(src), "r"(bytes), "r"(mbar) : "memory");
}
#define MBARRIER_WAIT_PARITY(mbar_smem_addr, phase_parity) do { \
    uint32_t _mbar = (uint32_t)(mbar_smem_addr); \
    uint32_t _parity = (uint32_t)(phase_parity); \
    uint32_t _done; \
    asm volatile("{\n\t.reg .pred p;\n\t" \
        "mbarrier.try_wait.parity.acquire.cta.shared::cta.b64 p, [%1], %2;\n\t" \
        "selp.b32 %0, 1, 0, p;\n\t}" \
        : "=r"(_done) : "r"(_mbar), "r"(_parity) : "memory"); \
    if (!_done) { \
        asm volatile("{\n\t.reg .pred P1;\n\t" \
            "WAIT_LOOP_%=:\n\t" \
            "mbarrier.try_wait.parity.acquire.cta.shared::cta.b64 P1, [%0], %1, 0x989680;\n\t" \
            "@P1 bra.uni WAIT_DONE_%=;\n\t" \
            "bra.uni WAIT_LOOP_%=;\n\t" \
            "WAIT_DONE_%=:\n\t}" \
            :: "r"(_mbar), "r"(_parity) : "memory"); \
    } \
} while (0)

// ---------------- kernel 1: fp32 -> fp16 pack into tile-major pre-swizzled blocks ------
__global__ void __launch_bounds__(256)
lstm_conv_kernel(const float* __restrict__ x,   const float* __restrict__ h,
                 const float* __restrict__ Wix, const float* __restrict__ Wmx,
                 const float* __restrict__ Wox, const float* __restrict__ Wih,
                 const float* __restrict__ Wmh, const float* __restrict__ Woh)
{
    const uint32_t i = blockIdx.x * 256u + threadIdx.x;   // 16B-chunk index
    const float* src;
    uint32_t dstElem;                                     // element offset into g_AW
    if (i < A_CHUNKS) {
        // A: [m_tile 0..127][kc][r 0..63][cc 0..7], block = 8KB pre-swizzled
        uint32_t mt  = i >> 15;            // 32768 chunks per m_tile (64 kc x 512)
        uint32_t rem = i & 32767u;
        uint32_t kc  = rem >> 9;
        uint32_t rc  = rem & 511u;
        uint32_t r   = rc >> 3;
        uint32_t cc  = rc & 7u;
        uint32_t m   = mt * 64u + r;
        uint32_t k   = kc * 64u + cc * 8u;
        src = (k < 2048u ? x : h) + (size_t)m * 2048u + (k & 2047u);
        dstElem = (mt * 64u + kc) * 4096u
                + (sw128((r << 7) + (cc << 4)) >> 1);
    } else {
        // W: [n_tile][kc][g 0..2][r 0..63][cc 0..7], block = 24KB pre-swizzled
        uint32_t j   = i - A_CHUNKS;
        uint32_t nt  = j / 98304u;
        uint32_t rem = j % 98304u;
        uint32_t kc  = rem / 1536u;
        uint32_t rc  = rem % 1536u;
        uint32_t g   = rc >> 9;
        uint32_t r   = (rc >> 3) & 63u;
        uint32_t cc  = rc & 7u;
        uint32_t n   = nt * 64u + r;
        uint32_t k   = kc * 64u + cc * 8u;
        const float* Wx  = (g == 0 ? Wix : (g == 1 ? Wmx : Wox));
        const float* Wh2 = (g == 0 ? Wih : (g == 1 ? Wmh : Woh));
        src = (k < 2048u ? Wx : Wh2) + (size_t)n * 2048u + (k & 2047u);
        dstElem = A_ELEMS + (nt * 64u + kc) * 12288u
                + g * 4096u
                + (sw128((r << 7) + (cc << 4)) >> 1);
    }
    float4 v0 = *(const float4*)src;
    float4 v1 = *(const float4*)(src + 4);
    __half2 p0 = __floats2half2_rn(v0.x, v0.y);
    __half2 p1 = __floats2half2_rn(v0.z, v0.w);
    __half2 p2 = __floats2half2_rn(v1.x, v1.y);
    __half2 p3 = __floats2half2_rn(v1.z, v1.w);
    uint4 pk;
    pk.x = *(const uint32_t*)&p0;
    pk.y = *(const uint32_t*)&p1;
    pk.z = *(const uint32_t*)&p2;
    pk.w = *(const uint32_t*)&p3;
    *(uint4*)(g_AW + dstElem) = pk;
}

// ---------------- kernel 2: fused 3-gate warp-MMA GEMM + LSTM epilogue ----------------
// M64 x N64 x 3 gates per CTA, 128 threads (4 warps along N), 2 CTAs/SM.
__global__ void __launch_bounds__(NTHREADS, 2)
lstm_gemm_kernel(const float* __restrict__ c,
                 const float* __restrict__ bix, const float* __restrict__ bmx,
                 const float* __restrict__ box_,
                 const float* __restrict__ bih, const float* __restrict__ bmh,
                 const float* __restrict__ boh,
                 float* __restrict__ out)
{
    extern __shared__ char smem[];
    const uint32_t sb = smem_u32(smem);
    float* sbias = (float*)smem;                  // [3][64] gate bias sums at offset 0
    const uint32_t mbar0 = sb + 800;              // 3 mbarriers at 800..824

    const int tid  = threadIdx.x;
    const int wn   = tid >> 5;       // 4 warps along N (16 cols each); all span M64
    const int lane = tid & 31;

    const uint32_t n_tile = blockIdx.x & 31;     // n fastest -> W blocks L2-resident
    const uint32_t m_tile = blockIdx.x >> 5;     // 0..127
    const int n0 = (int)(n_tile << 6);
    const int m0 = (int)(m_tile << 6);

    for (int t = tid; t < 192; t += NTHREADS) {
        int g  = t >> 6;
        int nl = t & 63;
        int n  = n0 + nl;
        const float* bx = (g == 0 ? bix : (g == 1 ? bmx : box_));
        const float* bh = (g == 0 ? bih : (g == 1 ? bmh : boh));
        sbias[t] = bx[n] + bh[n];
    }
    if (tid == 0) {
#pragma unroll
        for (int p = 0; p < NSTAGE; ++p) MBARRIER_INIT(mbar0 + p * 8, 1);
    }
    __syncthreads();

    // stage source pointers (packed, pre-swizzled, contiguous blocks)
    const char* srcA0 = (const char*)g_AW + (size_t)(m_tile * 64u) * A_STG;
    const char* srcB0 = (const char*)g_AW + (size_t)A_ELEMS * 2u
                      + (size_t)(n_tile * 64u) * B_STG;

    auto issue_stage = [&](int s) {    // single-thread, 2 bulk copies
        const int st = s % NSTAGE;
        const uint32_t stb = sb + 1024 + (uint32_t)st * STAGE_BYTES;
        const uint32_t mb  = mbar0 + (uint32_t)st * 8;
        MBARRIER_EXPECT_TX(mb, STAGE_BYTES);
        bulk_cp(stb,         srcA0 + (size_t)s * A_STG, A_STG, mb);
        bulk_cp(stb + A_STG, srcB0 + (size_t)s * B_STG, B_STG, mb);
    };

    if (tid == 0) {
        issue_stage(0);
        issue_stage(1);
    }

    // ---- consumer addressing (R8/R11-validated swizzle-hoist scheme) ----
    const uint32_t kbl  = (uint32_t)((lane >> 4) << 4);
    const uint32_t mask = (uint32_t)((lane & 7) << 4);
    const int rA = lane & 15;                 // M64: rows rA + i*16
    const int rB = wn * 16 + (lane & 15);
    uint32_t baseA[4], baseB[3];
#pragma unroll
    for (int i = 0; i < 4; ++i)
        baseA[i] = (uint32_t)((rA + i * 16) << 7);
#pragma unroll
    for (int g = 0; g < 3; ++g)
        baseB[g] = (uint32_t)A_STG + (uint32_t)g * 8192u + (uint32_t)(rB << 7);

    // ---- accumulators: [gate][m16 block][n8 block][4] ----
    float acc[3][4][2][4];
#pragma unroll
    for (int g = 0; g < 3; ++g)
#pragma unroll
        for (int i = 0; i < 4; ++i)
#pragma unroll
            for (int j = 0; j < 2; ++j)
#pragma unroll
                for (int v = 0; v < 4; ++v) acc[g][i][j][v] = 0.f;

    // ---- double-buffered fragments (ks-level software pipeline) ----
    uint32_t fA[2][4][4];
    uint32_t fB[2][3][4];

    auto ldfrag = [&](uint32_t sbase, int ks, int buf) {
        const uint32_t xcol = (kbl + (uint32_t)(ks * 32)) ^ mask;
#pragma unroll
        for (int i = 0; i < 4; ++i)
            ldsm4(fA[buf][i], sbase + baseA[i] + xcol);
#pragma unroll
        for (int g = 0; g < 3; ++g)
            ldsm4(fB[buf][g], sbase + baseB[g] + xcol);
    };
    auto domma = [&](int buf) {
#pragma unroll
        for (int g = 0; g < 3; ++g)
#pragma unroll
            for (int i = 0; i < 4; ++i) {
                mma16816(acc[g][i][0], fA[buf][i], fB[buf][g][0], fB[buf][g][2]);
                mma16816(acc[g][i][1], fA[buf][i], fB[buf][g][1], fB[buf][g][3]);
            }
    };

    // ---- main loop: ldsm(ks+1) before mma(ks); last burst issued after the
    //      next-stage wait + ks0 ldsm so those hide under it ----
    MBARRIER_WAIT_PARITY(mbar0, 0u);
    ldfrag(sb + 1024, 0, 0);

    for (int s = 0; s < KITERS; ++s) {
        const uint32_t sbase = sb + 1024 + (uint32_t)(s % NSTAGE) * STAGE_BYTES;
        ldfrag(sbase, 1, 1);  domma(0);     // mma ks0 under ldsm ks1
        ldfrag(sbase, 2, 0);  domma(1);     // mma ks1 under ldsm ks2
        ldfrag(sbase, 3, 1);  domma(0);     // mma ks2 under ldsm ks3
        __syncthreads();                    // all smem reads of stage s issued
        if (tid == 0 && s + 2 < KITERS) issue_stage(s + 2);
        if (s + 1 < KITERS) {
            const int sn = s + 1;
            MBARRIER_WAIT_PARITY(mbar0 + (uint32_t)(sn % NSTAGE) * 8,
                                 (uint32_t)((sn / NSTAGE) & 1));
            ldfrag(sb + 1024 + (uint32_t)(sn % NSTAGE) * STAGE_BYTES, 0, 0);
        }
        domma(1);                           // mma ks3 covers wait + next ks0 ldsm
    }

    // ---- fused LSTM epilogue (fully register-local) ----
    const int quad = lane >> 2;
    const int tc   = lane & 3;
#pragma unroll
    for (int i = 0; i < 4; ++i) {
#pragma unroll
        for (int hh = 0; hh < 2; ++hh) {
            const int m = m0 + i * 16 + quad + hh * 8;
            const float* crow = c   + (size_t)m * DH;
            float*       hrow = out + (size_t)m * DH;
            float*       nrow = out + (size_t)8192 * DH + (size_t)m * DH;
#pragma unroll
            for (int j = 0; j < 2; ++j) {
                const int nl = wn * 16 + j * 8 + tc * 2;
                const int n  = n0 + nl;
                float2 c2 = *(const float2*)(crow + n);
                float hn[2], cn[2];
#pragma unroll
                for (int e = 0; e < 2; ++e) {
                    float gi = acc[0][i][j][hh * 2 + e] + sbias[nl + e];
                    float gm = acc[1][i][j][hh * 2 + e] + sbias[64 + nl + e];
                    float go = acc[2][i][j][hh * 2 + e] + sbias[128 + nl + e];
                    float is = sigf(gi);
                    float fs = sigf(gm);
                    float ms = tanhe(gm);
                    float os = sigf(go);
                    float cold = (e == 0 ? c2.x : c2.y);
                    float cc = fs * cold + is * ms;
                    cn[e] = cc;
                    hn[e] = os * tanhe(cc);
                }
                *(float2*)(hrow + n) = make_float2(hn[0], hn[1]);
                *(float2*)(nrow + n) = make_float2(cn[0], cn[1]);
            }
        }
    }
}

// ---------------- launch ----------------
extern "C" void kernel_launch(void* const* d_in, const int* in_sizes, int n_in,
                              void* d_out, int out_size) {
    const float* x   = (const float*)d_in[0];
    const float* h   = (const float*)d_in[1];
    const float* c   = (const float*)d_in[2];
    const float* Wix = (const float*)d_in[3];
    const float* bix = (const float*)d_in[4];
    const float* Wmx = (const float*)d_in[5];
    const float* bmx = (const float*)d_in[6];
    const float* Wox = (const float*)d_in[7];
    const float* box_= (const float*)d_in[8];
    const float* Wih = (const float*)d_in[9];
    const float* bih = (const float*)d_in[10];
    const float* Wmh = (const float*)d_in[11];
    const float* bmh = (const float*)d_in[12];
    const float* Woh = (const float*)d_in[13];
    const float* boh = (const float*)d_in[14];
    float* out = (float*)d_out;

    cudaFuncSetAttribute(lstm_gemm_kernel,
                         cudaFuncAttributeMaxDynamicSharedMemorySize, SMEM_TOTAL);

    lstm_conv_kernel<<<TOT_CHUNKS / 256, 256>>>(x, h, Wix, Wmx, Wox, Wih, Wmh, Woh);
    lstm_gemm_kernel<<<4096, NTHREADS, SMEM_TOTAL>>>(c, bix, bmx, box_, bih, bmh, boh, out);
}

// round 14
// speedup vs baseline: 1.0618x; 1.0618x over previous
#include <cuda_runtime.h>
#include <cuda_fp16.h>
#include <cstdint>

// ---------------- problem constants ----------------
#define DH        2048
#define KTOT      4096            // concat(x,h) K
#define KITERS    32              // 4096 / 128 (KC=128 per stage, 8 ks sub-steps)
#define MT        128             // CTA M tile
#define NT        64              // CTA N tile
#define A_KCB     16384           // packed A kc-block bytes (128 rows x 128B)
#define B_KCB     24576           // packed W kc-block bytes (3 x 64 rows x 128B)
#define A_HALF    32768           // A bytes per stage (2 kc-blocks)
#define B_HALF    49152           // B bytes per stage (2 kc-blocks)
#define STAGE_BYTES  (A_HALF + B_HALF)                 // 81920
#define SMEM_TOTAL   (1024 + 2 * STAGE_BYTES)          // 164864
#define NTHREADS  256

#define A_ELEMS   (8192u * 4096u)          // 33,554,432
#define W_ELEMS   (3u * 2048u * 4096u)     // 25,165,824
#define A_CHUNKS  4194304u                 // 16B chunks in packed A
#define W_CHUNKS  3145728u                 // 16B chunks in packed W
#define TOT_CHUNKS (A_CHUNKS + W_CHUNKS)   // 7,340,032 = 28672 * 256

// ---------------- scratch: packed, tile-major, PRE-SWIZZLED operand store --------------
// A blocks: [m_tile 0..63][kc 0..63] -> 16384 B each (128 rows x 128B)
// W blocks: [n_tile 0..31][kc 0..63] -> 24576 B each, after A (A_ELEMS elems)
__device__ __align__(1024) __half g_AW[A_ELEMS + W_ELEMS];

// ---------------- helpers ----------------
static __device__ __forceinline__ uint32_t smem_u32(const void* p) {
    uint32_t a;
    asm("{ .reg .u64 t; cvta.to.shared.u64 t, %1; cvt.u32.u64 %0, t; }" : "=r"(a) : "l"(p));
    return a;
}
static __device__ __forceinline__ void ldsm4(uint32_t* r, uint32_t addr) {
    asm volatile("ldmatrix.sync.aligned.m8n8.x4.shared.b16 {%0,%1,%2,%3}, [%4];"
                 : "=r"(r[0]), "=r"(r[1]), "=r"(r[2]), "=r"(r[3]) : "r"(addr));
}
static __device__ __forceinline__ void mma16816(float* c4, const uint32_t* a,
                                                uint32_t b0, uint32_t b1) {
    asm volatile(
        "mma.sync.aligned.m16n8k16.row.col.f32.f16.f16.f32 "
        "{%0,%1,%2,%3}, {%4,%5,%6,%7}, {%8,%9}, {%0,%1,%2,%3};"
        : "+f"(c4[0]), "+f"(c4[1]), "+f"(c4[2]), "+f"(c4[3])
        : "r"(a[0]), "r"(a[1]), "r"(a[2]), "r"(a[3]), "r"(b0), "r"(b1));
}
static __device__ __forceinline__ float sigf(float x) {
    return __fdividef(1.f, 1.f + __expf(-x));
}
static __device__ __forceinline__ float tanhe(float x) {
    float t = __expf(2.f * x);
    return __fdividef(t - 1.f, t + 1.f);
}
static __device__ __forceinline__ uint32_t sw128(uint32_t off) {
    return off ^ ((off >> 3) & 0x70);
}

#define MBARRIER_INIT(addr, cnt) \
    asm volatile("mbarrier.init.shared.b64 [%0], %1;" \
        :: "r"((uint32_t)(addr)), "r"((uint32_t)(cnt)) : "memory")
#define MBARRIER_EXPECT_TX(addr, bytes) \
    asm volatile("mbarrier.arrive.expect_tx.shared.b64 _, [%0], %1;" \
        :: "r"((uint32_t)(addr)), "r"((uint32_t)(bytes)) : "memory")
static __device__ __forceinline__ void bulk_cp(uint32_t dst, const void* src,
                                               uint32_t bytes, uint32_t mbar) {
    asm volatile(
        "cp.async.bulk.shared::cluster.global.mbarrier::complete_tx::bytes "
        "[%0], [%1], %2, [%3];"
        :: "r"(dst), "l"(src), "r"(bytes), "r"(mbar) : "memory");
}
#define MBARRIER_WAIT_PARITY(mbar_smem_addr, phase_parity) do { \
    uint32_t _mbar = (uint32_t)(mbar_smem_addr); \
    uint32_t _parity = (uint32_t)(phase_parity); \
    uint32_t _done; \
    asm volatile("{\n\t.reg .pred p;\n\t" \
        "mbarrier.try_wait.parity.acquire.cta.shared::cta.b64 p, [%1], %2;\n\t" \
        "selp.b32 %0, 1, 0, p;\n\t}" \
        : "=r"(_done) : "r"(_mbar), "r"(_parity) : "memory"); \
    if (!_done) { \
        asm volatile("{\n\t.reg .pred P1;\n\t" \
            "WAIT_LOOP_%=:\n\t" \
            "mbarrier.try_wait.parity.acquire.cta.shared::cta.b64 P1, [%0], %1, 0x989680;\n\t" \
            "@P1 bra.uni WAIT_DONE_%=;\n\t" \
            "bra.uni WAIT_LOOP_%=;\n\t" \
            "WAIT_DONE_%=:\n\t}" \
            :: "r"(_mbar), "r"(_parity) : "memory"); \
    } \
} while (0)

// ---------------- kernel 1: fp32 -> fp16 pack into tile-major pre-swizzled blocks ------
// (identical to the validated R12 layout: A blocks 16KB, W blocks 24KB, kc-granular)
__global__ void __launch_bounds__(256)
lstm_conv_kernel(const float* __restrict__ x,   const float* __restrict__ h,
                 const float* __restrict__ Wix, const float* __restrict__ Wmx,
                 const float* __restrict__ Wox, const float* __restrict__ Wih,
                 const float* __restrict__ Wmh, const float* __restrict__ Woh)
{
    const uint32_t i = blockIdx.x * 256u + threadIdx.x;   // 16B-chunk index
    const float* src;
    uint32_t dstElem;                                     // element offset into g_AW
    if (i < A_CHUNKS) {
        // A: [m_tile][kc][r 0..127][cc 0..7], block = 16KB pre-swizzled
        uint32_t mt  = i >> 16;            // 65536 chunks per m_tile
        uint32_t rem = i & 65535u;
        uint32_t kc  = rem >> 10;
        uint32_t rc  = rem & 1023u;
        uint32_t r   = rc >> 3;
        uint32_t cc  = rc & 7u;
        uint32_t m   = mt * 128u + r;
        uint32_t k   = kc * 64u + cc * 8u;
        src = (k < 2048u ? x : h) + (size_t)m * 2048u + (k & 2047u);
        dstElem = (mt * 64u + kc) * 8192u
                + (sw128((r << 7) + (cc << 4)) >> 1);
    } else {
        // W: [n_tile][kc][g 0..2][r 0..63][cc 0..7], block = 24KB pre-swizzled
        uint32_t j   = i - A_CHUNKS;
        uint32_t nt  = j / 98304u;
        uint32_t rem = j % 98304u;
        uint32_t kc  = rem / 1536u;
        uint32_t rc  = rem % 1536u;
        uint32_t g   = rc >> 9;
        uint32_t r   = (rc >> 3) & 63u;
        uint32_t cc  = rc & 7u;
        uint32_t n   = nt * 64u + r;
        uint32_t k   = kc * 64u + cc * 8u;
        const float* Wx  = (g == 0 ? Wix : (g == 1 ? Wmx : Wox));
        const float* Wh2 = (g == 0 ? Wih : (g == 1 ? Wmh : Woh));
        src = (k < 2048u ? Wx : Wh2) + (size_t)n * 2048u + (k & 2047u);
        dstElem = A_ELEMS + (nt * 64u + kc) * 12288u
                + g * 4096u
                + (sw128((r << 7) + (cc << 4)) >> 1);
    }
    float4 v0 = *(const float4*)src;
    float4 v1 = *(const float4*)(src + 4);
    __half2 p0 = __floats2half2_rn(v0.x, v0.y);
    __half2 p1 = __floats2half2_rn(v0.z, v0.w);
    __half2 p2 = __floats2half2_rn(v1.x, v1.y);
    __half2 p3 = __floats2half2_rn(v1.z, v1.w);
    uint4 pk;
    pk.x = *(const uint32_t*)&p0;
    pk.y = *(const uint32_t*)&p1;
    pk.z = *(const uint32_t*)&p2;
    pk.w = *(const uint32_t*)&p3;
    *(uint4*)(g_AW + dstElem) = pk;
}

// ---------------- kernel 2: fused 3-gate warp-MMA GEMM + LSTM epilogue ----------------
// M128 x N64 x 3 gates per CTA, 256 threads, KC=128/stage (8 ks), 2-half smem ring.
__global__ void __launch_bounds__(NTHREADS, 1)
lstm_gemm_kernel(const float* __restrict__ c,
                 const float* __restrict__ bix, const float* __restrict__ bmx,
                 const float* __restrict__ box_,
                 const float* __restrict__ bih, const float* __restrict__ bmh,
                 const float* __restrict__ boh,
                 float* __restrict__ out)
{
    extern __shared__ char smem[];
    const uint32_t sb = smem_u32(smem);
    float* sbias = (float*)smem;                  // [3][64] gate bias sums at offset 0
    const uint32_t mbar0 = sb + 800;              // 2 mbarriers at 800..816

    const int tid  = threadIdx.x;
    const int wid  = tid >> 5;
    const int lane = tid & 31;
    const int wm   = wid & 1;        // 2 warps along M (64 rows each)
    const int wn   = wid >> 1;       // 4 warps along N (16 cols each)

    const uint32_t n_tile = blockIdx.x & 31;     // n fastest -> W blocks L2-resident
    const uint32_t m_tile = blockIdx.x >> 5;
    const int n0 = (int)(n_tile << 6);
    const int m0 = (int)(m_tile << 7);

    if (tid < 192) {
        int g  = tid >> 6;
        int nl = tid & 63;
        int n  = n0 + nl;
        const float* bx = (g == 0 ? bix : (g == 1 ? bmx : box_));
        const float* bh = (g == 0 ? bih : (g == 1 ? bmh : boh));
        sbias[tid] = bx[n] + bh[n];
    }
    if (tid == 0) {
        MBARRIER_INIT(mbar0, 1);
        MBARRIER_INIT(mbar0 + 8, 1);
    }
    __syncthreads();

    // stage source pointers: stage s = 2 consecutive kc-blocks (contiguous bytes)
    const char* srcA0 = (const char*)g_AW + (size_t)(m_tile * 64u) * A_KCB;
    const char* srcB0 = (const char*)g_AW + (size_t)A_ELEMS * 2u
                      + (size_t)(n_tile * 64u) * B_KCB;

    auto issue_stage = [&](int s) {    // single-thread, 2 bulk copies (80KB total)
        const int st = s & 1;
        const uint32_t stb = sb + 1024 + (uint32_t)st * STAGE_BYTES;
        const uint32_t mb  = mbar0 + (uint32_t)st * 8;
        MBARRIER_EXPECT_TX(mb, STAGE_BYTES);
        bulk_cp(stb,          srcA0 + (size_t)s * A_HALF, A_HALF, mb);
        bulk_cp(stb + A_HALF, srcB0 + (size_t)s * B_HALF, B_HALF, mb);
    };

    if (tid == 0) issue_stage(0);

    // ---- consumer addressing (validated swizzle-hoist scheme) ----
    const uint32_t kbl  = (uint32_t)((lane >> 4) << 4);
    const uint32_t mask = (uint32_t)((lane & 7) << 4);
    const int rA = wm * 64 + (lane & 15);
    const int rB = wn * 16 + (lane & 15);
    uint32_t baseA[4], baseB[3];
#pragma unroll
    for (int i = 0; i < 4; ++i)
        baseA[i] = (uint32_t)((rA + i * 16) << 7);
#pragma unroll
    for (int g = 0; g < 3; ++g)
        baseB[g] = (uint32_t)g * 8192u + (uint32_t)(rB << 7);

    // ---- accumulators: [gate][m16 block][n8 block][4] ----
    float acc[3][4][2][4];
#pragma unroll
    for (int g = 0; g < 3; ++g)
#pragma unroll
        for (int i = 0; i < 4; ++i)
#pragma unroll
            for (int j = 0; j < 2; ++j)
#pragma unroll
                for (int v = 0; v < 4; ++v) acc[g][i][j][v] = 0.f;

    // ---- double-buffered fragments (ks-level software pipeline) ----
    uint32_t fA[2][4][4];
    uint32_t fB[2][3][4];

    // ks in [0,8): kc-sub-block = ks>>2 (compile-time), column = ks&3
    auto ldfrag = [&](uint32_t sbase, int ks, int buf) {
        const uint32_t aoff = sbase + (uint32_t)((ks >> 2) * A_KCB);
        const uint32_t boff = sbase + (uint32_t)A_HALF + (uint32_t)((ks >> 2) * B_KCB);
        const uint32_t xcol = (kbl + (uint32_t)((ks & 3) * 32)) ^ mask;
#pragma unroll
        for (int i = 0; i < 4; ++i)
            ldsm4(fA[buf][i], aoff + baseA[i] + xcol);
#pragma unroll
        for (int g = 0; g < 3; ++g)
            ldsm4(fB[buf][g], boff + baseB[g] + xcol);
    };
    auto domma = [&](int buf) {
#pragma unroll
        for (int g = 0; g < 3; ++g)
#pragma unroll
            for (int i = 0; i < 4; ++i) {
                mma16816(acc[g][i][0], fA[buf][i], fB[buf][g][0], fB[buf][g][2]);
                mma16816(acc[g][i][1], fA[buf][i], fB[buf][g][1], fB[buf][g][3]);
            }
    };

    // ---- prologue: wait stage 0, preload its ks0 ----
    MBARRIER_WAIT_PARITY(mbar0, 0u);
    ldfrag(sb + 1024, 0, 0);

    // ---- main loop: 32 stages x 8 ks; one sync + one wait per stage ----
    for (int s = 0; s < KITERS; ++s) {
        const uint32_t sbase = sb + 1024 + (uint32_t)(s & 1) * STAGE_BYTES;
        __syncthreads();   // all warps consumed stage s-1 -> its half reusable
        if (tid == 0 && s + 1 < KITERS) issue_stage(s + 1);
        ldfrag(sbase, 1, 1);  domma(0);
        ldfrag(sbase, 2, 0);  domma(1);
        ldfrag(sbase, 3, 1);  domma(0);
        ldfrag(sbase, 4, 0);  domma(1);
        ldfrag(sbase, 5, 1);  domma(0);
        ldfrag(sbase, 6, 0);  domma(1);
        ldfrag(sbase, 7, 1);  domma(0);
        if (s + 1 < KITERS) {   // hoist next-stage wait + its ks0 under final burst
            MBARRIER_WAIT_PARITY(mbar0 + (uint32_t)((s + 1) & 1) * 8,
                                 (uint32_t)(((s + 1) >> 1) & 1));
            ldfrag(sb + 1024 + (uint32_t)((s + 1) & 1) * STAGE_BYTES, 0, 0);
        }
        domma(1);
    }

    // ---- fused LSTM epilogue (fully register-local) ----
    const int quad = lane >> 2;
    const int tc   = lane & 3;
#pragma unroll
    for (int i = 0; i < 4; ++i) {
#pragma unroll
        for (int hh = 0; hh < 2; ++hh) {
            const int m = m0 + wm * 64 + i * 16 + quad + hh * 8;
            const float* crow = c   + (size_t)m * DH;
            float*       hrow = out + (size_t)m * DH;
            float*       nrow = out + (size_t)8192 * DH + (size_t)m * DH;
#pragma unroll
            for (int j = 0; j < 2; ++j) {
                const int nl = wn * 16 + j * 8 + tc * 2;
                const int n  = n0 + nl;
                float2 c2 = *(const float2*)(crow + n);
                float hn[2], cn[2];
#pragma unroll
                for (int e = 0; e < 2; ++e) {
                    float gi = acc[0][i][j][hh * 2 + e] + sbias[nl + e];
                    float gm = acc[1][i][j][hh * 2 + e] + sbias[64 + nl + e];
                    float go = acc[2][i][j][hh * 2 + e] + sbias[128 + nl + e];
                    float is = sigf(gi);
                    float fs = sigf(gm);
                    float ms = tanhe(gm);
                    float os = sigf(go);
                    float cold = (e == 0 ? c2.x : c2.y);
                    float cc = fs * cold + is * ms;
                    cn[e] = cc;
                    hn[e] = os * tanhe(cc);
                }
                *(float2*)(hrow + n) = make_float2(hn[0], hn[1]);
                *(float2*)(nrow + n) = make_float2(cn[0], cn[1]);
            }
        }
    }
}

// ---------------- launch ----------------
extern "C" void kernel_launch(void* const* d_in, const int* in_sizes, int n_in,
                              void* d_out, int out_size) {
    const float* x   = (const float*)d_in[0];
    const float* h   = (const float*)d_in[1];
    const float* c   = (const float*)d_in[2];
    const float* Wix = (const float*)d_in[3];
    const float* bix = (const float*)d_in[4];
    const float* Wmx = (const float*)d_in[5];
    const float* bmx = (const float*)d_in[6];
    const float* Wox = (const float*)d_in[7];
    const float* box_= (const float*)d_in[8];
    const float* Wih = (const float*)d_in[9];
    const float* bih = (const float*)d_in[10];
    const float* Wmh = (const float*)d_in[11];
    const float* bmh = (const float*)d_in[12];
    const float* Woh = (const float*)d_in[13];
    const float* boh = (const float*)d_in[14];
    float* out = (float*)d_out;

    cudaFuncSetAttribute(lstm_gemm_kernel,
                         cudaFuncAttributeMaxDynamicSharedMemorySize, SMEM_TOTAL);

    lstm_conv_kernel<<<TOT_CHUNKS / 256, 256>>>(x, h, Wix, Wmx, Wox, Wih, Wmh, Woh);
    lstm_gemm_kernel<<<2048, NTHREADS, SMEM_TOTAL>>>(c, bix, bmx, box_, bih, bmh, boh, out);
}

// round 15
// speedup vs baseline: 1.1093x; 1.0447x over previous
#include <cuda_runtime.h>
#include <cuda_fp16.h>
#include <cstdint>

// ---------------- problem constants ----------------
#define DH        2048
#define KTOT      4096            // concat(x,h) K
#define KITERS    32              // 4096 / 128 (KC=128 per stage, 8 ks sub-steps)
#define MT        128             // CTA M tile
#define NT        64              // CTA N tile
#define A_KCB     16384           // packed A kc-block bytes (128 rows x 128B)
#define B_KCB     24576           // packed W kc-block bytes (3 x 64 rows x 128B)
#define A_HALF    32768           // A bytes per stage (2 kc-blocks)
#define B_HALF    49152           // B bytes per stage (2 kc-blocks)
#define STAGE_BYTES  (A_HALF + B_HALF)                 // 81920
#define SMEM_TOTAL   (1024 + 2 * STAGE_BYTES)          // 164864
#define NTHREADS  256

#define A_ELEMS   (8192u * 4096u)          // 33,554,432
#define W_ELEMS   (3u * 2048u * 4096u)     // 25,165,824
#define A_CHUNKS  4194304u                 // 16B chunks in packed A
#define W_CHUNKS  3145728u                 // 16B chunks in packed W
#define TOT_CHUNKS (A_CHUNKS + W_CHUNKS)   // 7,340,032 = 28672 * 256

// ---------------- scratch: packed, tile-major, PRE-SWIZZLED operand store --------------
// A blocks: [m_tile 0..63][kc 0..63] -> 16384 B each (128 rows x 128B)
// W blocks: [n_tile 0..31][kc 0..63] -> 24576 B each, after A (A_ELEMS elems)
__device__ __align__(1024) __half g_AW[A_ELEMS + W_ELEMS];

// ---------------- helpers ----------------
static __device__ __forceinline__ uint32_t smem_u32(const void* p) {
    uint32_t a;
    asm("{ .reg .u64 t; cvta.to.shared.u64 t, %1; cvt.u32.u64 %0, t; }" : "=r"(a) : "l"(p));
    return a;
}
static __device__ __forceinline__ void ldsm4(uint32_t* r, uint32_t addr) {
    asm volatile("ldmatrix.sync.aligned.m8n8.x4.shared.b16 {%0,%1,%2,%3}, [%4];"
                 : "=r"(r[0]), "=r"(r[1]), "=r"(r[2]), "=r"(r[3]) : "r"(addr));
}
static __device__ __forceinline__ void mma16816(float* c4, const uint32_t* a,
                                                uint32_t b0, uint32_t b1) {
    asm volatile(
        "mma.sync.aligned.m16n8k16.row.col.f32.f16.f16.f32 "
        "{%0,%1,%2,%3}, {%4,%5,%6,%7}, {%8,%9}, {%0,%1,%2,%3};"
        : "+f"(c4[0]), "+f"(c4[1]), "+f"(c4[2]), "+f"(c4[3])
        : "r"(a[0]), "r"(a[1]), "r"(a[2]), "r"(a[3]), "r"(b0), "r"(b1));
}
static __device__ __forceinline__ float sigf(float x) {
    return __fdividef(1.f, 1.f + __expf(-x));
}
static __device__ __forceinline__ float tanhe(float x) {
    float t = __expf(2.f * x);
    return __fdividef(t - 1.f, t + 1.f);
}
static __device__ __forceinline__ uint32_t sw128(uint32_t off) {
    return off ^ ((off >> 3) & 0x70);
}

#define MBARRIER_INIT(addr, cnt) \
    asm volatile("mbarrier.init.shared.b64 [%0], %1;" \
        :: "r"((uint32_t)(addr)), "r"((uint32_t)(cnt)) : "memory")
#define MBARRIER_EXPECT_TX(addr, bytes) \
    asm volatile("mbarrier.arrive.expect_tx.shared.b64 _, [%0], %1;" \
        :: "r"((uint32_t)(addr)), "r"((uint32_t)(bytes)) : "memory")
static __device__ __forceinline__ void bulk_cp(uint32_t dst, const void* src,
                                               uint32_t bytes, uint32_t mbar) {
    asm volatile(
        "cp.async.bulk.shared::cluster.global.mbarrier::complete_tx::bytes "
        "[%0], [%1], %2, [%3];"
        :: "r"(dst), "l"(src), "r"(bytes), "r"(mbar) : "memory");
}
#define MBARRIER_WAIT_PARITY(mbar_smem_addr, phase_parity) do { \
    uint32_t _mbar = (uint32_t)(mbar_smem_addr); \
    uint32_t _parity = (uint32_t)(phase_parity); \
    uint32_t _done; \
    asm volatile("{\n\t.reg .pred p;\n\t" \
        "mbarrier.try_wait.parity.acquire.cta.shared::cta.b64 p, [%1], %2;\n\t" \
        "selp.b32 %0, 1, 0, p;\n\t}" \
        : "=r"(_done) : "r"(_mbar), "r"(_parity) : "memory"); \
    if (!_done) { \
        asm volatile("{\n\t.reg .pred P1;\n\t" \
            "WAIT_LOOP_%=:\n\t" \
            "mbarrier.try_wait.parity.acquire.cta.shared::cta.b64 P1, [%0], %1, 0x989680;\n\t" \
            "@P1 bra.uni WAIT_DONE_%=;\n\t" \
            "bra.uni WAIT_LOOP_%=;\n\t" \
            "WAIT_DONE_%=:\n\t}" \
            :: "r"(_mbar), "r"(_parity) : "memory"); \
    } \
} while (0)

// producer/consumer named barrier (id 1, all 256 threads)
#define BAR_ARRIVE() asm volatile("bar.arrive 1, 256;" ::: "memory")
#define BAR_SYNC()   asm volatile("bar.sync 1, 256;"   ::: "memory")

// ---------------- kernel 1: fp32 -> fp16 pack into tile-major pre-swizzled blocks ------
__global__ void __launch_bounds__(256)
lstm_conv_kernel(const float* __restrict__ x,   const float* __restrict__ h,
                 const float* __restrict__ Wix, const float* __restrict__ Wmx,
                 const float* __restrict__ Wox, const float* __restrict__ Wih,
                 const float* __restrict__ Wmh, const float* __restrict__ Woh)
{
    const uint32_t i = blockIdx.x * 256u + threadIdx.x;   // 16B-chunk index
    const float* src;
    uint32_t dstElem;                                     // element offset into g_AW
    if (i < A_CHUNKS) {
        // A: [m_tile][kc][r 0..127][cc 0..7], block = 16KB pre-swizzled
        uint32_t mt  = i >> 16;            // 65536 chunks per m_tile
        uint32_t rem = i & 65535u;
        uint32_t kc  = rem >> 10;
        uint32_t rc  = rem & 1023u;
        uint32_t r   = rc >> 3;
        uint32_t cc  = rc & 7u;
        uint32_t m   = mt * 128u + r;
        uint32_t k   = kc * 64u + cc * 8u;
        src = (k < 2048u ? x : h) + (size_t)m * 2048u + (k & 2047u);
        dstElem = (mt * 64u + kc) * 8192u
                + (sw128((r << 7) + (cc << 4)) >> 1);
    } else {
        // W: [n_tile][kc][g 0..2][r 0..63][cc 0..7], block = 24KB pre-swizzled
        uint32_t j   = i - A_CHUNKS;
        uint32_t nt  = j / 98304u;
        uint32_t rem = j % 98304u;
        uint32_t kc  = rem / 1536u;
        uint32_t rc  = rem % 1536u;
        uint32_t g   = rc >> 9;
        uint32_t r   = (rc >> 3) & 63u;
        uint32_t cc  = rc & 7u;
        uint32_t n   = nt * 64u + r;
        uint32_t k   = kc * 64u + cc * 8u;
        const float* Wx  = (g == 0 ? Wix : (g == 1 ? Wmx : Wox));
        const float* Wh2 = (g == 0 ? Wih : (g == 1 ? Wmh : Woh));
        src = (k < 2048u ? Wx : Wh2) + (size_t)n * 2048u + (k & 2047u);
        dstElem = A_ELEMS + (nt * 64u + kc) * 12288u
                + g * 4096u
                + (sw128((r << 7) + (cc << 4)) >> 1);
    }
    float4 v0 = *(const float4*)src;
    float4 v1 = *(const float4*)(src + 4);
    __half2 p0 = __floats2half2_rn(v0.x, v0.y);
    __half2 p1 = __floats2half2_rn(v0.z, v0.w);
    __half2 p2 = __floats2half2_rn(v1.x, v1.y);
    __half2 p3 = __floats2half2_rn(v1.z, v1.w);
    uint4 pk;
    pk.x = *(const uint32_t*)&p0;
    pk.y = *(const uint32_t*)&p1;
    pk.z = *(const uint32_t*)&p2;
    pk.w = *(const uint32_t*)&p3;
    *(uint4*)(g_AW + dstElem) = pk;
}

// ---------------- kernel 2: fused 3-gate warp-MMA GEMM + LSTM epilogue ----------------
// M128 x N64 x 3 gates per CTA, 256 threads, KC=128/stage (8 ks), 2-half smem ring.
// Stage boundary: warps 1-7 bar.arrive (non-blocking); warp 0 bar.sync before the
// producer TMA reuses the freed half. Consumers only block on the (hoisted) full-wait.
__global__ void __launch_bounds__(NTHREADS, 1)
lstm_gemm_kernel(const float* __restrict__ c,
                 const float* __restrict__ bix, const float* __restrict__ bmx,
                 const float* __restrict__ box_,
                 const float* __restrict__ bih, const float* __restrict__ bmh,
                 const float* __restrict__ boh,
                 float* __restrict__ out)
{
    extern __shared__ char smem[];
    const uint32_t sb = smem_u32(smem);
    float* sbias = (float*)smem;                  // [3][64] gate bias sums at offset 0
    const uint32_t mbar0 = sb + 800;              // 2 full-barriers at 800..816

    const int tid  = threadIdx.x;
    const int wid  = tid >> 5;
    const int lane = tid & 31;
    const int wm   = wid & 1;        // 2 warps along M (64 rows each)
    const int wn   = wid >> 1;       // 4 warps along N (16 cols each)

    const uint32_t n_tile = blockIdx.x & 31;     // n fastest -> W blocks L2-resident
    const uint32_t m_tile = blockIdx.x >> 5;
    const int n0 = (int)(n_tile << 6);
    const int m0 = (int)(m_tile << 7);

    if (tid < 192) {
        int g  = tid >> 6;
        int nl = tid & 63;
        int n  = n0 + nl;
        const float* bx = (g == 0 ? bix : (g == 1 ? bmx : box_));
        const float* bh = (g == 0 ? bih : (g == 1 ? bmh : boh));
        sbias[tid] = bx[n] + bh[n];
    }
    if (tid == 0) {
        MBARRIER_INIT(mbar0, 1);
        MBARRIER_INIT(mbar0 + 8, 1);
    }
    __syncthreads();

    // stage source pointers: stage s = 2 consecutive kc-blocks (contiguous bytes)
    const char* srcA0 = (const char*)g_AW + (size_t)(m_tile * 64u) * A_KCB;
    const char* srcB0 = (const char*)g_AW + (size_t)A_ELEMS * 2u
                      + (size_t)(n_tile * 64u) * B_KCB;

    auto issue_stage = [&](int s) {    // single-thread, 2 bulk copies (80KB total)
        const int st = s & 1;
        const uint32_t stb = sb + 1024 + (uint32_t)st * STAGE_BYTES;
        const uint32_t mb  = mbar0 + (uint32_t)st * 8;
        MBARRIER_EXPECT_TX(mb, STAGE_BYTES);
        bulk_cp(stb,          srcA0 + (size_t)s * A_HALF, A_HALF, mb);
        bulk_cp(stb + A_HALF, srcB0 + (size_t)s * B_HALF, B_HALF, mb);
    };

    if (tid == 0) issue_stage(0);

    // ---- consumer addressing (validated swizzle-hoist scheme) ----
    const uint32_t kbl  = (uint32_t)((lane >> 4) << 4);
    const uint32_t mask = (uint32_t)((lane & 7) << 4);
    const int rA = wm * 64 + (lane & 15);
    const int rB = wn * 16 + (lane & 15);
    uint32_t baseA[4], baseB[3];
#pragma unroll
    for (int i = 0; i < 4; ++i)
        baseA[i] = (uint32_t)((rA + i * 16) << 7);
#pragma unroll
    for (int g = 0; g < 3; ++g)
        baseB[g] = (uint32_t)g * 8192u + (uint32_t)(rB << 7);

    // ---- accumulators: [gate][m16 block][n8 block][4] ----
    float acc[3][4][2][4];
#pragma unroll
    for (int g = 0; g < 3; ++g)
#pragma unroll
        for (int i = 0; i < 4; ++i)
#pragma unroll
            for (int j = 0; j < 2; ++j)
#pragma unroll
                for (int v = 0; v < 4; ++v) acc[g][i][j][v] = 0.f;

    // ---- double-buffered fragments (ks-level software pipeline) ----
    uint32_t fA[2][4][4];
    uint32_t fB[2][3][4];

    // ks in [0,8): kc-sub-block = ks>>2 (compile-time), column = ks&3
    auto ldfrag = [&](uint32_t sbase, int ks, int buf) {
        const uint32_t aoff = sbase + (uint32_t)((ks >> 2) * A_KCB);
        const uint32_t boff = sbase + (uint32_t)A_HALF + (uint32_t)((ks >> 2) * B_KCB);
        const uint32_t xcol = (kbl + (uint32_t)((ks & 3) * 32)) ^ mask;
#pragma unroll
        for (int i = 0; i < 4; ++i)
            ldsm4(fA[buf][i], aoff + baseA[i] + xcol);
#pragma unroll
        for (int g = 0; g < 3; ++g)
            ldsm4(fB[buf][g], boff + baseB[g] + xcol);
    };
    auto domma = [&](int buf) {
#pragma unroll
        for (int g = 0; g < 3; ++g)
#pragma unroll
            for (int i = 0; i < 4; ++i) {
                mma16816(acc[g][i][0], fA[buf][i], fB[buf][g][0], fB[buf][g][2]);
                mma16816(acc[g][i][1], fA[buf][i], fB[buf][g][1], fB[buf][g][3]);
            }
    };

    // ---- prologue: wait stage 0, preload its ks0 ----
    MBARRIER_WAIT_PARITY(mbar0, 0u);
    ldfrag(sb + 1024, 0, 0);

    // ---- main loop: 32 stages x 8 ks ----
    // top of stage s (s>=1): warp 0 syncs on arrivals from end of stage s-1,
    // then tid 0 issues stage s+1 into the freed half. Stage 1 needs no bar
    // (its half is untouched).  End of stage s: warps 1-7 arrive (non-blocking).
    for (int s = 0; s < KITERS; ++s) {
        const uint32_t sbase = sb + 1024 + (uint32_t)(s & 1) * STAGE_BYTES;
        if (s + 1 < KITERS) {
            if (s >= 1 && wid == 0) BAR_SYNC();
            if (tid == 0) issue_stage(s + 1);
        }
        ldfrag(sbase, 1, 1);  domma(0);
        ldfrag(sbase, 2, 0);  domma(1);
        ldfrag(sbase, 3, 1);  domma(0);
        ldfrag(sbase, 4, 0);  domma(1);
        ldfrag(sbase, 5, 1);  domma(0);
        ldfrag(sbase, 6, 0);  domma(1);
        ldfrag(sbase, 7, 1);  domma(0);
        if (s + 1 < KITERS) {   // hoist next-stage wait + its ks0 under final burst
            MBARRIER_WAIT_PARITY(mbar0 + (uint32_t)((s + 1) & 1) * 8,
                                 (uint32_t)(((s + 1) >> 1) & 1));
            ldfrag(sb + 1024 + (uint32_t)((s + 1) & 1) * STAGE_BYTES, 0, 0);
        }
        domma(1);               // consumes the last fragments of this stage's half
        if (wid != 0 && s + 2 < KITERS) BAR_ARRIVE();   // half (s&1) fully consumed
    }

    // ---- fused LSTM epilogue (fully register-local) ----
    const int quad = lane >> 2;
    const int tc   = lane & 3;
#pragma unroll
    for (int i = 0; i < 4; ++i) {
#pragma unroll
        for (int hh = 0; hh < 2; ++hh) {
            const int m = m0 + wm * 64 + i * 16 + quad + hh * 8;
            const float* crow = c   + (size_t)m * DH;
            float*       hrow = out + (size_t)m * DH;
            float*       nrow = out + (size_t)8192 * DH + (size_t)m * DH;
#pragma unroll
            for (int j = 0; j < 2; ++j) {
                const int nl = wn * 16 + j * 8 + tc * 2;
                const int n  = n0 + nl;
                float2 c2 = *(const float2*)(crow + n);
                float hn[2], cn[2];
#pragma unroll
                for (int e = 0; e < 2; ++e) {
                    float gi = acc[0][i][j][hh * 2 + e] + sbias[nl + e];
                    float gm = acc[1][i][j][hh * 2 + e] + sbias[64 + nl + e];
                    float go = acc[2][i][j][hh * 2 + e] + sbias[128 + nl + e];
                    float is = sigf(gi);
                    float fs = sigf(gm);
                    float ms = tanhe(gm);
                    float os = sigf(go);
                    float cold = (e == 0 ? c2.x : c2.y);
                    float cc = fs * cold + is * ms;
                    cn[e] = cc;
                    hn[e] = os * tanhe(cc);
                }
                *(float2*)(hrow + n) = make_float2(hn[0], hn[1]);
                *(float2*)(nrow + n) = make_float2(cn[0], cn[1]);
            }
        }
    }
}

// ---------------- launch ----------------
extern "C" void kernel_launch(void* const* d_in, const int* in_sizes, int n_in,
                              void* d_out, int out_size) {
    const float* x   = (const float*)d_in[0];
    const float* h   = (const float*)d_in[1];
    const float* c   = (const float*)d_in[2];
    const float* Wix = (const float*)d_in[3];
    const float* bix = (const float*)d_in[4];
    const float* Wmx = (const float*)d_in[5];
    const float* bmx = (const float*)d_in[6];
    const float* Wox = (const float*)d_in[7];
    const float* box_= (const float*)d_in[8];
    const float* Wih = (const float*)d_in[9];
    const float* bih = (const float*)d_in[10];
    const float* Wmh = (const float*)d_in[11];
    const float* bmh = (const float*)d_in[12];
    const float* Woh = (const float*)d_in[13];
    const float* boh = (const float*)d_in[14];
    float* out = (float*)d_out;

    cudaFuncSetAttribute(lstm_gemm_kernel,
                         cudaFuncAttributeMaxDynamicSharedMemorySize, SMEM_TOTAL);

    lstm_conv_kernel<<<TOT_CHUNKS / 256, 256>>>(x, h, Wix, Wmx, Wox, Wih, Wmh, Woh);
    lstm_gemm_kernel<<<2048, NTHREADS, SMEM_TOTAL>>>(c, bix, bmx, box_, bih, bmh, boh, out);
}

// round 16
// speedup vs baseline: 1.1352x; 1.0233x over previous
#include <cuda_runtime.h>
#include <cuda_fp16.h>
#include <cstdint>

// ---------------- problem constants ----------------
#define DH        2048
#define KTOT      4096            // concat(x,h) K
#define KITERS    32              // 4096 / 128 (KC=128 per stage, 8 ks sub-steps)
#define MT        128             // CTA M tile
#define NT        64              // CTA N tile
#define A_KCB     16384           // packed A kc-block bytes (128 rows x 128B)
#define B_KCB     24576           // packed W kc-block bytes (3 x 64 rows x 128B)
#define A_HALF    32768           // A bytes per stage (2 kc-blocks)
#define B_HALF    49152           // B bytes per stage (2 kc-blocks)
#define STAGE_BYTES  (A_HALF + B_HALF)                 // 81920
#define SMEM_TOTAL   (1024 + 2 * STAGE_BYTES)          // 164864
#define NTHREADS  256

#define A_ELEMS   (8192u * 4096u)          // 33,554,432
#define W_ELEMS   (3u * 2048u * 4096u)     // 25,165,824
#define A_CHUNKS  4194304u                 // 16B chunks in packed A
#define W_CHUNKS  3145728u                 // 16B chunks in packed W
#define TOT_CHUNKS (A_CHUNKS + W_CHUNKS)   // 7,340,032 = 28672 * 256

// ---------------- scratch: packed, tile-major, PRE-SWIZZLED operand store --------------
// A blocks: [m_tile 0..63][kc 0..63] -> 16384 B each (128 rows x 128B)
// W blocks: [n_tile 0..31][kc 0..63] -> 24576 B each, after A (A_ELEMS elems)
__device__ __align__(1024) __half g_AW[A_ELEMS + W_ELEMS];

// ---------------- helpers ----------------
static __device__ __forceinline__ uint32_t smem_u32(const void* p) {
    uint32_t a;
    asm("{ .reg .u64 t; cvta.to.shared.u64 t, %1; cvt.u32.u64 %0, t; }" : "=r"(a) : "l"(p));
    return a;
}
static __device__ __forceinline__ void ldsm4(uint32_t* r, uint32_t addr) {
    asm volatile("ldmatrix.sync.aligned.m8n8.x4.shared.b16 {%0,%1,%2,%3}, [%4];"
                 : "=r"(r[0]), "=r"(r[1]), "=r"(r[2]), "=r"(r[3]) : "r"(addr));
}
static __device__ __forceinline__ void mma16816(float* c4, const uint32_t* a,
                                                uint32_t b0, uint32_t b1) {
    asm volatile(
        "mma.sync.aligned.m16n8k16.row.col.f32.f16.f16.f32 "
        "{%0,%1,%2,%3}, {%4,%5,%6,%7}, {%8,%9}, {%0,%1,%2,%3};"
        : "+f"(c4[0]), "+f"(c4[1]), "+f"(c4[2]), "+f"(c4[3])
        : "r"(a[0]), "r"(a[1]), "r"(a[2]), "r"(a[3]), "r"(b0), "r"(b1));
}
// fast tanh (sm_75+ MUFU instruction, 1 op) and sigmoid via tanh identity
static __device__ __forceinline__ float tanha(float x) {
    float y;
    asm("tanh.approx.f32 %0, %1;" : "=f"(y) : "f"(x));
    return y;
}
static __device__ __forceinline__ float siga(float x) {
    return fmaf(tanha(0.5f * x), 0.5f, 0.5f);
}
static __device__ __forceinline__ uint32_t sw128(uint32_t off) {
    return off ^ ((off >> 3) & 0x70);
}

#define MBARRIER_INIT(addr, cnt) \
    asm volatile("mbarrier.init.shared.b64 [%0], %1;" \
        :: "r"((uint32_t)(addr)), "r"((uint32_t)(cnt)) : "memory")
#define MBARRIER_EXPECT_TX(addr, bytes) \
    asm volatile("mbarrier.arrive.expect_tx.shared.b64 _, [%0], %1;" \
        :: "r"((uint32_t)(addr)), "r"((uint32_t)(bytes)) : "memory")
static __device__ __forceinline__ void bulk_cp(uint32_t dst, const void* src,
                                               uint32_t bytes, uint32_t mbar) {
    asm volatile(
        "cp.async.bulk.shared::cluster.global.mbarrier::complete_tx::bytes "
        "[%0], [%1], %2, [%3];"
        :: "r"(dst), "l"(src), "r"(bytes), "r"(mbar) : "memory");
}
#define MBARRIER_WAIT_PARITY(mbar_smem_addr, phase_parity) do { \
    uint32_t _mbar = (uint32_t)(mbar_smem_addr); \
    uint32_t _parity = (uint32_t)(phase_parity); \
    uint32_t _done; \
    asm volatile("{\n\t.reg .pred p;\n\t" \
        "mbarrier.try_wait.parity.acquire.cta.shared::cta.b64 p, [%1], %2;\n\t" \
        "selp.b32 %0, 1, 0, p;\n\t}" \
        : "=r"(_done) : "r"(_mbar), "r"(_parity) : "memory"); \
    if (!_done) { \
        asm volatile("{\n\t.reg .pred P1;\n\t" \
            "WAIT_LOOP_%=:\n\t" \
            "mbarrier.try_wait.parity.acquire.cta.shared::cta.b64 P1, [%0], %1, 0x989680;\n\t" \
            "@P1 bra.uni WAIT_DONE_%=;\n\t" \
            "bra.uni WAIT_LOOP_%=;\n\t" \
            "WAIT_DONE_%=:\n\t}" \
            :: "r"(_mbar), "r"(_parity) : "memory"); \
    } \
} while (0)

// producer/consumer named barrier (id 1, all 256 threads)
#define BAR_ARRIVE() asm volatile("bar.arrive 1, 256;" ::: "memory")
#define BAR_SYNC()   asm volatile("bar.sync 1, 256;"   ::: "memory")

// ---------------- kernel 1: fp32 -> fp16 pack into tile-major pre-swizzled blocks ------
__global__ void __launch_bounds__(256)
lstm_conv_kernel(const float* __restrict__ x,   const float* __restrict__ h,
                 const float* __restrict__ Wix, const float* __restrict__ Wmx,
                 const float* __restrict__ Wox, const float* __restrict__ Wih,
                 const float* __restrict__ Wmh, const float* __restrict__ Woh)
{
    const uint32_t i = blockIdx.x * 256u + threadIdx.x;   // 16B-chunk index
    const float* src;
    uint32_t dstElem;                                     // element offset into g_AW
    if (i < A_CHUNKS) {
        // A: [m_tile][kc][r 0..127][cc 0..7], block = 16KB pre-swizzled
        uint32_t mt  = i >> 16;            // 65536 chunks per m_tile
        uint32_t rem = i & 65535u;
        uint32_t kc  = rem >> 10;
        uint32_t rc  = rem & 1023u;
        uint32_t r   = rc >> 3;
        uint32_t cc  = rc & 7u;
        uint32_t m   = mt * 128u + r;
        uint32_t k   = kc * 64u + cc * 8u;
        src = (k < 2048u ? x : h) + (size_t)m * 2048u + (k & 2047u);
        dstElem = (mt * 64u + kc) * 8192u
                + (sw128((r << 7) + (cc << 4)) >> 1);
    } else {
        // W: [n_tile][kc][g 0..2][r 0..63][cc 0..7], block = 24KB pre-swizzled
        uint32_t j   = i - A_CHUNKS;
        uint32_t nt  = j / 98304u;
        uint32_t rem = j % 98304u;
        uint32_t kc  = rem / 1536u;
        uint32_t rc  = rem % 1536u;
        uint32_t g   = rc >> 9;
        uint32_t r   = (rc >> 3) & 63u;
        uint32_t cc  = rc & 7u;
        uint32_t n   = nt * 64u + r;
        uint32_t k   = kc * 64u + cc * 8u;
        const float* Wx  = (g == 0 ? Wix : (g == 1 ? Wmx : Wox));
        const float* Wh2 = (g == 0 ? Wih : (g == 1 ? Wmh : Woh));
        src = (k < 2048u ? Wx : Wh2) + (size_t)n * 2048u + (k & 2047u);
        dstElem = A_ELEMS + (nt * 64u + kc) * 12288u
                + g * 4096u
                + (sw128((r << 7) + (cc << 4)) >> 1);
    }
    float4 v0 = *(const float4*)src;
    float4 v1 = *(const float4*)(src + 4);
    __half2 p0 = __floats2half2_rn(v0.x, v0.y);
    __half2 p1 = __floats2half2_rn(v0.z, v0.w);
    __half2 p2 = __floats2half2_rn(v1.x, v1.y);
    __half2 p3 = __floats2half2_rn(v1.z, v1.w);
    uint4 pk;
    pk.x = *(const uint32_t*)&p0;
    pk.y = *(const uint32_t*)&p1;
    pk.z = *(const uint32_t*)&p2;
    pk.w = *(const uint32_t*)&p3;
    *(uint4*)(g_AW + dstElem) = pk;
}

// ---------------- kernel 2: fused 3-gate warp-MMA GEMM + LSTM epilogue ----------------
// M128 x N64 x 3 gates per CTA, 256 threads, KC=128/stage (8 ks), 2-half smem ring.
// Stage boundary: warps 1-7 bar.arrive (non-blocking); warp 0 bar.sync before the
// producer TMA reuses the freed half. Consumers only block on the (hoisted) full-wait.
__global__ void __launch_bounds__(NTHREADS, 1)
lstm_gemm_kernel(const float* __restrict__ c,
                 const float* __restrict__ bix, const float* __restrict__ bmx,
                 const float* __restrict__ box_,
                 const float* __restrict__ bih, const float* __restrict__ bmh,
                 const float* __restrict__ boh,
                 float* __restrict__ out)
{
    extern __shared__ char smem[];
    const uint32_t sb = smem_u32(smem);
    float* sbias = (float*)smem;                  // [3][64] gate bias sums at offset 0
    const uint32_t mbar0 = sb + 800;              // 2 full-barriers at 800..816

    const int tid  = threadIdx.x;
    const int wid  = tid >> 5;
    const int lane = tid & 31;
    const int wm   = wid & 1;        // 2 warps along M (64 rows each)
    const int wn   = wid >> 1;       // 4 warps along N (16 cols each)

    const uint32_t n_tile = blockIdx.x & 31;     // n fastest -> W blocks L2-resident
    const uint32_t m_tile = blockIdx.x >> 5;
    const int n0 = (int)(n_tile << 6);
    const int m0 = (int)(m_tile << 7);

    if (tid < 192) {
        int g  = tid >> 6;
        int nl = tid & 63;
        int n  = n0 + nl;
        const float* bx = (g == 0 ? bix : (g == 1 ? bmx : box_));
        const float* bh = (g == 0 ? bih : (g == 1 ? bmh : boh));
        sbias[tid] = bx[n] + bh[n];
    }
    if (tid == 0) {
        MBARRIER_INIT(mbar0, 1);
        MBARRIER_INIT(mbar0 + 8, 1);
    }
    __syncthreads();

    // stage source pointers: stage s = 2 consecutive kc-blocks (contiguous bytes)
    const char* srcA0 = (const char*)g_AW + (size_t)(m_tile * 64u) * A_KCB;
    const char* srcB0 = (const char*)g_AW + (size_t)A_ELEMS * 2u
                      + (size_t)(n_tile * 64u) * B_KCB;

    auto issue_stage = [&](int s) {    // single-thread, 2 bulk copies (80KB total)
        const int st = s & 1;
        const uint32_t stb = sb + 1024 + (uint32_t)st * STAGE_BYTES;
        const uint32_t mb  = mbar0 + (uint32_t)st * 8;
        MBARRIER_EXPECT_TX(mb, STAGE_BYTES);
        bulk_cp(stb,          srcA0 + (size_t)s * A_HALF, A_HALF, mb);
        bulk_cp(stb + A_HALF, srcB0 + (size_t)s * B_HALF, B_HALF, mb);
    };

    if (tid == 0) issue_stage(0);

    // ---- consumer addressing (validated swizzle-hoist scheme) ----
    const uint32_t kbl  = (uint32_t)((lane >> 4) << 4);
    const uint32_t mask = (uint32_t)((lane & 7) << 4);
    const int rA = wm * 64 + (lane & 15);
    const int rB = wn * 16 + (lane & 15);
    uint32_t baseA[4], baseB[3];
#pragma unroll
    for (int i = 0; i < 4; ++i)
        baseA[i] = (uint32_t)((rA + i * 16) << 7);
#pragma unroll
    for (int g = 0; g < 3; ++g)
        baseB[g] = (uint32_t)g * 8192u + (uint32_t)(rB << 7);

    // ---- accumulators: [gate][m16 block][n8 block][4] ----
    float acc[3][4][2][4];
#pragma unroll
    for (int g = 0; g < 3; ++g)
#pragma unroll
        for (int i = 0; i < 4; ++i)
#pragma unroll
            for (int j = 0; j < 2; ++j)
#pragma unroll
                for (int v = 0; v < 4; ++v) acc[g][i][j][v] = 0.f;

    // ---- double-buffered fragments (ks-level software pipeline) ----
    uint32_t fA[2][4][4];
    uint32_t fB[2][3][4];

    // ks in [0,8): kc-sub-block = ks>>2 (compile-time), column = ks&3
    auto ldfrag = [&](uint32_t sbase, int ks, int buf) {
        const uint32_t aoff = sbase + (uint32_t)((ks >> 2) * A_KCB);
        const uint32_t boff = sbase + (uint32_t)A_HALF + (uint32_t)((ks >> 2) * B_KCB);
        const uint32_t xcol = (kbl + (uint32_t)((ks & 3) * 32)) ^ mask;
#pragma unroll
        for (int i = 0; i < 4; ++i)
            ldsm4(fA[buf][i], aoff + baseA[i] + xcol);
#pragma unroll
        for (int g = 0; g < 3; ++g)
            ldsm4(fB[buf][g], boff + baseB[g] + xcol);
    };
    auto domma = [&](int buf) {
#pragma unroll
        for (int g = 0; g < 3; ++g)
#pragma unroll
            for (int i = 0; i < 4; ++i) {
                mma16816(acc[g][i][0], fA[buf][i], fB[buf][g][0], fB[buf][g][2]);
                mma16816(acc[g][i][1], fA[buf][i], fB[buf][g][1], fB[buf][g][3]);
            }
    };

    // ---- prologue: wait stage 0, preload its ks0 ----
    MBARRIER_WAIT_PARITY(mbar0, 0u);
    ldfrag(sb + 1024, 0, 0);

    // ---- main loop: 32 stages x 8 ks ----
    for (int s = 0; s < KITERS; ++s) {
        const uint32_t sbase = sb + 1024 + (uint32_t)(s & 1) * STAGE_BYTES;
        if (s + 1 < KITERS) {
            if (s >= 1 && wid == 0) BAR_SYNC();
            if (tid == 0) issue_stage(s + 1);
        }
        ldfrag(sbase, 1, 1);  domma(0);
        ldfrag(sbase, 2, 0);  domma(1);
        ldfrag(sbase, 3, 1);  domma(0);
        ldfrag(sbase, 4, 0);  domma(1);
        ldfrag(sbase, 5, 1);  domma(0);
        ldfrag(sbase, 6, 0);  domma(1);
        ldfrag(sbase, 7, 1);  domma(0);
        if (s + 1 < KITERS) {   // hoist next-stage wait + its ks0 under final burst
            MBARRIER_WAIT_PARITY(mbar0 + (uint32_t)((s + 1) & 1) * 8,
                                 (uint32_t)(((s + 1) >> 1) & 1));
            ldfrag(sb + 1024 + (uint32_t)((s + 1) & 1) * STAGE_BYTES, 0, 0);
        }
        domma(1);               // consumes the last fragments of this stage's half
        if (wid != 0 && s + 2 < KITERS) BAR_ARRIVE();   // half (s&1) fully consumed
    }

    // ---- fused LSTM epilogue (register-local, tanh.approx transcendentals) ----
    const int quad = lane >> 2;
    const int tc   = lane & 3;
#pragma unroll
    for (int i = 0; i < 4; ++i) {
#pragma unroll
        for (int hh = 0; hh < 2; ++hh) {
            const int m = m0 + wm * 64 + i * 16 + quad + hh * 8;
            const float* crow = c   + (size_t)m * DH;
            float*       hrow = out + (size_t)m * DH;
            float*       nrow = out + (size_t)8192 * DH + (size_t)m * DH;
#pragma unroll
            for (int j = 0; j < 2; ++j) {
                const int nl = wn * 16 + j * 8 + tc * 2;
                const int n  = n0 + nl;
                float2 c2 = *(const float2*)(crow + n);
                float hn[2], cn[2];
#pragma unroll
                for (int e = 0; e < 2; ++e) {
                    float gi = acc[0][i][j][hh * 2 + e] + sbias[nl + e];
                    float gm = acc[1][i][j][hh * 2 + e] + sbias[64 + nl + e];
                    float go = acc[2][i][j][hh * 2 + e] + sbias[128 + nl + e];
                    float is = siga(gi);
                    float fs = siga(gm);
                    float ms = tanha(gm);
                    float os = siga(go);
                    float cold = (e == 0 ? c2.x : c2.y);
                    float cc = fs * cold + is * ms;
                    cn[e] = cc;
                    hn[e] = os * tanha(cc);
                }
                *(float2*)(hrow + n) = make_float2(hn[0], hn[1]);
                *(float2*)(nrow + n) = make_float2(cn[0], cn[1]);
            }
        }
    }
}

// ---------------- launch ----------------
extern "C" void kernel_launch(void* const* d_in, const int* in_sizes, int n_in,
                              void* d_out, int out_size) {
    const float* x   = (const float*)d_in[0];
    const float* h   = (const float*)d_in[1];
    const float* c   = (const float*)d_in[2];
    const float* Wix = (const float*)d_in[3];
    const float* bix = (const float*)d_in[4];
    const float* Wmx = (const float*)d_in[5];
    const float* bmx = (const float*)d_in[6];
    const float* Wox = (const float*)d_in[7];
    const float* box_= (const float*)d_in[8];
    const float* Wih = (const float*)d_in[9];
    const float* bih = (const float*)d_in[10];
    const float* Wmh = (const float*)d_in[11];
    const float* bmh = (const float*)d_in[12];
    const float* Woh = (const float*)d_in[13];
    const float* boh = (const float*)d_in[14];
    float* out = (float*)d_out;

    cudaFuncSetAttribute(lstm_gemm_kernel,
                         cudaFuncAttributeMaxDynamicSharedMemorySize, SMEM_TOTAL);

    lstm_conv_kernel<<<TOT_CHUNKS / 256, 256>>>(x, h, Wix, Wmx, Wox, Wih, Wmh, Woh);
    lstm_gemm_kernel<<<2048, NTHREADS, SMEM_TOTAL>>>(c, bix, bmx, box_, bih, bmh, boh, out);
}